// round 1
// baseline (speedup 1.0000x reference)
#include <cuda_runtime.h>

#define NT 2560
#define D 32
#define NB 4
#define BN 64
#define BM 64
#define NTHREADS 256

// Inter-layer scratch (device global: allocation-free per harness rules)
__device__ float g_h1[NB * NT * D];

__device__ __forceinline__ float tanh_relu(float s) {
    // tanh(relu(s)): exact for s<=0; accurate exp-based tanh for s>0
    if (s <= 0.0f) return 0.0f;
    float t = __expf(-2.0f * s);
    return __fdividef(1.0f - t, 1.0f + t);
}

__global__ __launch_bounds__(NTHREADS, 2)
void fused_layer_kernel(const float* __restrict__ X,
                        const float* __restrict__ Hin_p,   // nullptr -> g_h1
                        const float* __restrict__ Ws,      // [32,32] this layer
                        const float* __restrict__ Wn,      // [32,32] this layer
                        const float* __restrict__ bias,    // [32] this layer
                        float* __restrict__ Hout_p)        // nullptr -> g_h1
{
    __shared__ float sXnT[D][BN + 4];   // X rows of this block, transposed [k][r]
    __shared__ float sXmT[D][BM + 4];   // X rows of current m-tile, transposed [k][c]
    __shared__ float sHm[BM][D];        // H rows of current m-tile [m][d]
    __shared__ float sST[BM][BN + 4];   // S transposed [c][r]; reused for agg in epilogue

    const int b  = blockIdx.y;
    const int n0 = blockIdx.x * BN;
    const int t  = threadIdx.x;
    const int rg = t >> 4;     // 0..15 : row group (4 rows)
    const int cg = t & 15;     // 0..15 : col group

    const float* Hin  = Hin_p  ? Hin_p  : (const float*)g_h1;
    float*       Hout = Hout_p ? Hout_p : g_h1;

    const float* Xb = X   + b * NT * D;
    const float* Hb = Hin + b * NT * D;

    // ---- Load Xn tile (rows n0..n0+63) transposed into sXnT[k][r] ----
    #pragma unroll
    for (int i = 0; i < 2; ++i) {
        int idx = t + i * NTHREADS;          // 0..511
        int r = idx >> 3, kq = idx & 7;      // r 0..63, kq 0..7
        float4 v = *reinterpret_cast<const float4*>(Xb + (n0 + r) * D + kq * 4);
        sXnT[kq * 4 + 0][r] = v.x; sXnT[kq * 4 + 1][r] = v.y;
        sXnT[kq * 4 + 2][r] = v.z; sXnT[kq * 4 + 3][r] = v.w;
    }

    float agg[4][2];
    #pragma unroll
    for (int i = 0; i < 4; ++i) { agg[i][0] = 0.0f; agg[i][1] = 0.0f; }

    for (int mt = 0; mt < NT / BM; ++mt) {
        const int m0 = mt * BM;
        __syncthreads();   // previous phase-2 done reading sHm/sST (and covers Xn fill on mt=0)

        // ---- Fill Xm (transposed) and Hm tiles ----
        #pragma unroll
        for (int i = 0; i < 2; ++i) {
            int idx = t + i * NTHREADS;
            int r = idx >> 3, kq = idx & 7;
            float4 xv = *reinterpret_cast<const float4*>(Xb + (m0 + r) * D + kq * 4);
            sXmT[kq * 4 + 0][r] = xv.x; sXmT[kq * 4 + 1][r] = xv.y;
            sXmT[kq * 4 + 2][r] = xv.z; sXmT[kq * 4 + 3][r] = xv.w;
            float4 hv = *reinterpret_cast<const float4*>(Hb + (m0 + r) * D + kq * 4);
            *reinterpret_cast<float4*>(&sHm[r][kq * 4]) = hv;
        }
        __syncthreads();

        // ---- Phase 1: S[4x4] = Xn_rows · Xm_cols ----
        float acc[4][4];
        #pragma unroll
        for (int i = 0; i < 4; ++i)
            #pragma unroll
            for (int j = 0; j < 4; ++j) acc[i][j] = 0.0f;

        #pragma unroll
        for (int k = 0; k < D; ++k) {
            float4 xn = *reinterpret_cast<const float4*>(&sXnT[k][4 * rg]);
            float4 xm = *reinterpret_cast<const float4*>(&sXmT[k][4 * cg]);
            float xnv[4] = {xn.x, xn.y, xn.z, xn.w};
            float xmv[4] = {xm.x, xm.y, xm.z, xm.w};
            #pragma unroll
            for (int i = 0; i < 4; ++i)
                #pragma unroll
                for (int j = 0; j < 4; ++j)
                    acc[i][j] += xnv[i] * xmv[j];
        }

        // ---- Nonlinearity + self-loop, store S transposed ----
        #pragma unroll
        for (int j = 0; j < 4; ++j) {
            const int c = 4 * cg + j;
            float vals[4];
            #pragma unroll
            for (int i = 0; i < 4; ++i) {
                float v = tanh_relu(acc[i][j]);
                if (n0 + 4 * rg + i == m0 + c) v += 0.5f;   // SELF_LOOP_EPS
                vals[i] = v;
            }
            *reinterpret_cast<float4*>(&sST[c][4 * rg]) =
                make_float4(vals[0], vals[1], vals[2], vals[3]);
        }
        __syncthreads();

        // ---- Phase 2: agg[4x2] += S^T rows · Hm ----
        #pragma unroll 16
        for (int m = 0; m < BM; ++m) {
            float4 sv = *reinterpret_cast<const float4*>(&sST[m][4 * rg]);
            float2 hv = *reinterpret_cast<const float2*>(&sHm[m][2 * cg]);
            agg[0][0] += sv.x * hv.x; agg[0][1] += sv.x * hv.y;
            agg[1][0] += sv.y * hv.x; agg[1][1] += sv.y * hv.y;
            agg[2][0] += sv.z * hv.x; agg[2][1] += sv.z * hv.y;
            agg[3][0] += sv.w * hv.x; agg[3][1] += sv.w * hv.y;
        }
    }

    __syncthreads();

    // ---- Stash agg into sST (stride BN+4 keeps epilogue reads conflict-free) ----
    #pragma unroll
    for (int i = 0; i < 4; ++i) {
        sST[4 * rg + i][2 * cg + 0] = agg[i][0];
        sST[4 * rg + i][2 * cg + 1] = agg[i][1];
    }

    // ---- Load layer weights into (dead) sXmT region ----
    float* sW = &sXmT[0][0];                 // [0,1024)=Ws, [1024,2048)=Wn, [2048,2080)=b
    for (int i = t; i < 2 * D * D + D; i += NTHREADS) {
        float v;
        if (i < D * D)          v = Ws[i];
        else if (i < 2 * D * D) v = Wn[i - D * D];
        else                    v = bias[i - 2 * D * D];
        sW[i] = v;
    }
    __syncthreads();

    // ---- Epilogue: out = elu(Hin·Ws + agg·Wn + b) ----
    const int r  = t >> 2;            // 0..63
    const int e0 = (t & 3) * 8;       // 0,8,16,24
    float out[8];
    #pragma unroll
    for (int e = 0; e < 8; ++e) out[e] = sW[2 * D * D + e0 + e];

    const float* hrow = Hb + (n0 + r) * D;
    #pragma unroll
    for (int d = 0; d < D; ++d) {
        const float hv = __ldg(hrow + d);
        const float av = sST[r][d];
        const float* ws = sW + d * D + e0;
        const float* wn = sW + D * D + d * D + e0;
        #pragma unroll
        for (int e = 0; e < 8; ++e)
            out[e] += hv * ws[e] + av * wn[e];
    }
    #pragma unroll
    for (int e = 0; e < 8; ++e) {
        float v = out[e];
        out[e] = v > 0.0f ? v : (__expf(v) - 1.0f);   // ELU(alpha=1)
    }
    float* orow = Hout + (b * NT + n0 + r) * D + e0;
    *reinterpret_cast<float4*>(orow)     = make_float4(out[0], out[1], out[2], out[3]);
    *reinterpret_cast<float4*>(orow + 4) = make_float4(out[4], out[5], out[6], out[7]);
}

extern "C" void kernel_launch(void* const* d_in, const int* in_sizes, int n_in,
                              void* d_out, int out_size) {
    (void)in_sizes; (void)n_in; (void)out_size;
    const float* X  = (const float*)d_in[0];
    const float* Ws = (const float*)d_in[1];   // [2,32,32]
    const float* Wn = (const float*)d_in[2];   // [2,32,32]
    const float* bb = (const float*)d_in[3];   // [2,32]
    float* out = (float*)d_out;

    dim3 grid(NT / BN, NB), block(NTHREADS);
    // Layer 0: Hin = X, Hout = g_h1 (nullptr sentinel)
    fused_layer_kernel<<<grid, block>>>(X, X, Ws, Wn, bb, nullptr);
    // Layer 1: Hin = g_h1 (nullptr sentinel), Hout = d_out
    fused_layer_kernel<<<grid, block>>>(X, nullptr, Ws + D * D, Wn + D * D, bb + D, out);
}

// round 3
// speedup vs baseline: 2.6879x; 2.6879x over previous
#include <cuda_runtime.h>
#include <cuda_fp16.h>
#include <cstdint>

#define NT 2560
#define DD 32
#define NB 4
#define BN 64
#define BM 128
#define NITER (NT / BM)   // 20
#define NTHREADS 256

// ---- smem byte offsets (fp16 tiles padded: row stride 80B for 32-d rows,
//      272B for 128-m rows -> conflict-free fragment loads) ----
#define SM_XNH 0
#define SM_XNL (SM_XNH + 64 * 80)      // 5120
#define SM_XMH (SM_XNL + 64 * 80)      // 10240
#define SM_XML (SM_XMH + 128 * 80)     // 20480
#define SM_HTH (SM_XML + 128 * 80)     // 30720
#define SM_HTL (SM_HTH + 32 * 272)     // 39424
#define SM_W   (SM_HTL + 32 * 272)     // 48128  (Ws|Wn|bias fp32)
#define SM_AGG SM_XMH                  // 32KB agg buffers reuse Xm+HT region
#define SMEM_TOTAL (SM_W + 8320)       // 56448

__device__ float g_h1[NB * NT * DD];   // inter-layer scratch

__device__ __forceinline__ void mma16816(float c[4], const uint32_t a[4],
                                         const uint32_t b[2]) {
  asm volatile(
      "mma.sync.aligned.m16n8k16.row.col.f32.f16.f16.f32 "
      "{%0,%1,%2,%3}, {%4,%5,%6,%7}, {%8,%9}, {%0,%1,%2,%3};"
      : "+f"(c[0]), "+f"(c[1]), "+f"(c[2]), "+f"(c[3])
      : "r"(a[0]), "r"(a[1]), "r"(a[2]), "r"(a[3]), "r"(b[0]), "r"(b[1]));
}

__device__ __forceinline__ float tanh_relu(float s) {
  float r = fmaxf(s, 0.0f);
  float e = __expf(-2.0f * r);
  return __fdividef(1.0f - e, 1.0f + e);
}

__device__ __forceinline__ void pack_split(float x, float y,
                                           uint32_t& hi, uint32_t& lo) {
  __half2 h = __floats2half2_rn(x, y);
  float2 hf = __half22float2(h);
  __half2 l = __floats2half2_rn(x - hf.x, y - hf.y);
  hi = *reinterpret_cast<uint32_t*>(&h);
  lo = *reinterpret_cast<uint32_t*>(&l);
}

__global__ __launch_bounds__(NTHREADS, 2)
void gnn_wmma_kernel(const float* __restrict__ X,
                     const float* __restrict__ Hin_p,
                     const float* __restrict__ Ws,
                     const float* __restrict__ Wn,
                     const float* __restrict__ bias,
                     float* __restrict__ Hout_p)
{
  extern __shared__ char sm[];
  const int t = threadIdx.x, lane = t & 31, wid = t >> 5;
  const int wr = wid >> 2, wc = wid & 3;          // warp grid 2(n) x 4(m-slice)
  const int g = lane >> 2, tig = lane & 3;
  const int bx = blockIdx.x, b = blockIdx.y;
  const int n0 = bx * BN;
  const int doff = (bx & 1) * 64;
  const int mtdiag = bx >> 1;

  const float* Hin  = Hin_p  ? Hin_p  : (const float*)g_h1;
  float*       Hout = Hout_p ? Hout_p : g_h1;
  const float* Xb = X   + (size_t)b * NT * DD;
  const float* Hb = Hin + (size_t)b * NT * DD;

  // ---- weights -> smem ----
  float* sW = (float*)(sm + SM_W);
  for (int i = t; i < 2 * DD * DD + DD; i += NTHREADS) {
    float v;
    if (i < DD * DD)          v = Ws[i];
    else if (i < 2 * DD * DD) v = Wn[i - DD * DD];
    else                      v = bias[i - 2 * DD * DD];
    sW[i] = v;
  }

  // ---- Xn tile fill (once): 64 rows x 32 d, fp16 split ----
  {
    const int row = t >> 2, dq = (t & 3) * 8;
    const float4* src = (const float4*)(Xb + (size_t)(n0 + row) * DD + dq);
    float4 v0 = src[0], v1 = src[1];
    uint32_t h[4], l[4];
    pack_split(v0.x, v0.y, h[0], l[0]);
    pack_split(v0.z, v0.w, h[1], l[1]);
    pack_split(v1.x, v1.y, h[2], l[2]);
    pack_split(v1.z, v1.w, h[3], l[3]);
    *(uint4*)(sm + SM_XNH + row * 80 + dq * 2) = make_uint4(h[0], h[1], h[2], h[3]);
    *(uint4*)(sm + SM_XNL + row * 80 + dq * 2) = make_uint4(l[0], l[1], l[2], l[3]);
  }

  // per-lane fragment base offsets
  const int aoffB = (32 * wr + g) * 80 + tig * 4;   // A from Xn
  const int boff1 = (32 * wc + g) * 80 + tig * 4;   // B from Xm (phase 1)
  const int boff2 = g * 272 + 32 * wc * 2 + tig * 4; // B from HT (phase 2)

  float acc2[2][4][4];
  #pragma unroll
  for (int rt = 0; rt < 2; ++rt)
    #pragma unroll
    for (int nc = 0; nc < 4; ++nc)
      #pragma unroll
      for (int rg = 0; rg < 4; ++rg) acc2[rt][nc][rg] = 0.0f;

  for (int mt = 0; mt < NITER; ++mt) {
    const int m0 = mt * BM;
    if (mt) __syncthreads();   // prev phase-2 done before overwriting tiles

    // ---- Xm fill: 128 x 32, fp16 split ----
    {
      const int row = t >> 1, dq = (t & 1) * 16;
      const float4* src = (const float4*)(Xb + (size_t)(m0 + row) * DD + dq);
      uint32_t h[8], l[8];
      #pragma unroll
      for (int q = 0; q < 4; ++q) {
        float4 v = src[q];
        pack_split(v.x, v.y, h[2 * q],     l[2 * q]);
        pack_split(v.z, v.w, h[2 * q + 1], l[2 * q + 1]);
      }
      *(uint4*)(sm + SM_XMH + row * 80 + dq * 2)      = make_uint4(h[0], h[1], h[2], h[3]);
      *(uint4*)(sm + SM_XMH + row * 80 + dq * 2 + 16) = make_uint4(h[4], h[5], h[6], h[7]);
      *(uint4*)(sm + SM_XML + row * 80 + dq * 2)      = make_uint4(l[0], l[1], l[2], l[3]);
      *(uint4*)(sm + SM_XML + row * 80 + dq * 2 + 16) = make_uint4(l[4], l[5], l[6], l[7]);
    }
    // ---- HT fill: H m-tile transposed -> HT[d][m], fp16 split ----
    {
      const int d = t & 31;
      #pragma unroll
      for (int p = (t >> 5); p < 64; p += 8) {
        const int m = 2 * p;
        float v0 = Hb[(size_t)(m0 + m) * DD + d];
        float v1 = Hb[(size_t)(m0 + m + 1) * DD + d];
        uint32_t h, l;
        pack_split(v0, v1, h, l);
        *(uint32_t*)(sm + SM_HTH + d * 272 + m * 2) = h;
        *(uint32_t*)(sm + SM_HTL + d * 272 + m * 2) = l;
      }
    }
    __syncthreads();

    const bool diag = (mt == mtdiag);
    uint32_t sA2H[2][8], sA2L[2][8];   // phase-2 A fragments (S, fp16 split)

    // ---- Phase 1 in two m-halves (register pressure) ----
    #pragma unroll
    for (int half = 0; half < 2; ++half) {
      float acc[2][2][4];
      #pragma unroll
      for (int rt = 0; rt < 2; ++rt)
        #pragma unroll
        for (int mcl = 0; mcl < 2; ++mcl)
          #pragma unroll
          for (int rg = 0; rg < 4; ++rg) acc[rt][mcl][rg] = 0.0f;

      #pragma unroll
      for (int kt = 0; kt < 2; ++kt) {
        uint32_t AH[2][4], AL[2][4];
        #pragma unroll
        for (int rt = 0; rt < 2; ++rt) {
          const char* pH = sm + SM_XNH + aoffB + rt * 1280 + kt * 32;
          AH[rt][0] = *(const uint32_t*)(pH);
          AH[rt][1] = *(const uint32_t*)(pH + 640);
          AH[rt][2] = *(const uint32_t*)(pH + 16);
          AH[rt][3] = *(const uint32_t*)(pH + 656);
          const char* pL = sm + SM_XNL + aoffB + rt * 1280 + kt * 32;
          AL[rt][0] = *(const uint32_t*)(pL);
          AL[rt][1] = *(const uint32_t*)(pL + 640);
          AL[rt][2] = *(const uint32_t*)(pL + 16);
          AL[rt][3] = *(const uint32_t*)(pL + 656);
        }
        uint32_t BH[2][2], BL[2][2];
        #pragma unroll
        for (int mcl = 0; mcl < 2; ++mcl) {
          const int mc = half * 2 + mcl;
          const char* pH = sm + SM_XMH + boff1 + mc * 640 + kt * 32;
          BH[mcl][0] = *(const uint32_t*)(pH);
          BH[mcl][1] = *(const uint32_t*)(pH + 16);
          const char* pL = sm + SM_XML + boff1 + mc * 640 + kt * 32;
          BL[mcl][0] = *(const uint32_t*)(pL);
          BL[mcl][1] = *(const uint32_t*)(pL + 16);
        }
        #pragma unroll
        for (int rt = 0; rt < 2; ++rt)
          #pragma unroll
          for (int mcl = 0; mcl < 2; ++mcl) {
            mma16816(acc[rt][mcl], AH[rt], BH[mcl]);
            mma16816(acc[rt][mcl], AH[rt], BL[mcl]);
            mma16816(acc[rt][mcl], AL[rt], BH[mcl]);
          }
      }

      // tanh(relu) + self-loop, pack to phase-2 A frags (C->A register reuse)
      #pragma unroll
      for (int rt = 0; rt < 2; ++rt)
        #pragma unroll
        for (int mcl = 0; mcl < 2; ++mcl) {
          const int j = half * 2 + mcl;
          float v0 = tanh_relu(acc[rt][mcl][0]);
          float v1 = tanh_relu(acc[rt][mcl][1]);
          float v2 = tanh_relu(acc[rt][mcl][2]);
          float v3 = tanh_relu(acc[rt][mcl][3]);
          if (diag) {
            const int nl = 32 * wr + 16 * rt + g;
            const int ml = 32 * wc + 8 * j + 2 * tig;
            if (ml     == nl + doff)     v0 += 0.5f;
            if (ml + 1 == nl + doff)     v1 += 0.5f;
            if (ml     == nl + 8 + doff) v2 += 0.5f;
            if (ml + 1 == nl + 8 + doff) v3 += 0.5f;
          }
          pack_split(v0, v1, sA2H[rt][2 * j],     sA2L[rt][2 * j]);
          pack_split(v2, v3, sA2H[rt][2 * j + 1], sA2L[rt][2 * j + 1]);
        }
    }

    // ---- Phase 2: agg += S (regs) x H (HT smem), split 3-pass ----
    #pragma unroll
    for (int kt = 0; kt < 2; ++kt) {
      uint32_t BH[4][2], BL[4][2];
      #pragma unroll
      for (int nc = 0; nc < 4; ++nc) {
        const char* pH = sm + SM_HTH + boff2 + nc * 2176 + kt * 32;
        BH[nc][0] = *(const uint32_t*)(pH);
        BH[nc][1] = *(const uint32_t*)(pH + 16);
        const char* pL = sm + SM_HTL + boff2 + nc * 2176 + kt * 32;
        BL[nc][0] = *(const uint32_t*)(pL);
        BL[nc][1] = *(const uint32_t*)(pL + 16);
      }
      #pragma unroll
      for (int rt = 0; rt < 2; ++rt)
        #pragma unroll
        for (int nc = 0; nc < 4; ++nc) {
          mma16816(acc2[rt][nc], &sA2H[rt][4 * kt], BH[nc]);
          mma16816(acc2[rt][nc], &sA2H[rt][4 * kt], BL[nc]);
          mma16816(acc2[rt][nc], &sA2L[rt][4 * kt], BH[nc]);
        }
    }
  }

  __syncthreads();   // all MMAs done; Xm/HT regions now dead -> agg buffers

  // ---- cross-warp (m-slice) reduction of agg ----
  float* aggbuf = (float*)(sm + SM_AGG);
  {
    float* p = aggbuf + wc * 2048;
    #pragma unroll
    for (int rt = 0; rt < 2; ++rt)
      #pragma unroll
      for (int nc = 0; nc < 4; ++nc) {
        const int nl = 32 * wr + 16 * rt + g;
        const int d0 = 8 * nc + 2 * tig;
        p[nl * 32 + d0]           = acc2[rt][nc][0];
        p[nl * 32 + d0 + 1]       = acc2[rt][nc][1];
        p[(nl + 8) * 32 + d0]     = acc2[rt][nc][2];
        p[(nl + 8) * 32 + d0 + 1] = acc2[rt][nc][3];
      }
  }
  __syncthreads();
  #pragma unroll
  for (int j = 0; j < 8; ++j) {
    const int i = t + j * 256;
    aggbuf[i] += aggbuf[i + 2048] + aggbuf[i + 4096] + aggbuf[i + 6144];
  }
  __syncthreads();

  // ---- epilogue: out = elu(h*Ws + agg*Wn + b) ----
  {
    const int r = t >> 2, e0 = (t & 3) * 8;
    float h[DD];
    const float4* hr = (const float4*)(Hb + (size_t)(n0 + r) * DD);
    #pragma unroll
    for (int q = 0; q < 8; ++q) {
      float4 v = hr[q];
      h[4 * q] = v.x; h[4 * q + 1] = v.y; h[4 * q + 2] = v.z; h[4 * q + 3] = v.w;
    }
    float out[8];
    #pragma unroll
    for (int e = 0; e < 8; ++e) out[e] = sW[2 * DD * DD + e0 + e];
    const float* ag = aggbuf + r * DD;
    #pragma unroll
    for (int d = 0; d < DD; ++d) {
      const float hd = h[d];
      const float ad = ag[d];
      const float* ws = sW + d * DD + e0;
      const float* wn = sW + DD * DD + d * DD + e0;
      #pragma unroll
      for (int e = 0; e < 8; ++e) out[e] += hd * ws[e] + ad * wn[e];
    }
    #pragma unroll
    for (int e = 0; e < 8; ++e) {
      float v = out[e];
      out[e] = v > 0.0f ? v : (__expf(v) - 1.0f);
    }
    float* orow = Hout + (size_t)((size_t)b * NT + n0 + r) * DD + e0;
    *(float4*)(orow)     = make_float4(out[0], out[1], out[2], out[3]);
    *(float4*)(orow + 4) = make_float4(out[4], out[5], out[6], out[7]);
  }
}

extern "C" void kernel_launch(void* const* d_in, const int* in_sizes, int n_in,
                              void* d_out, int out_size) {
  (void)in_sizes; (void)n_in; (void)out_size;
  const float* X  = (const float*)d_in[0];
  const float* Ws = (const float*)d_in[1];   // [2,32,32]
  const float* Wn = (const float*)d_in[2];   // [2,32,32]
  const float* bb = (const float*)d_in[3];   // [2,32]
  float* out = (float*)d_out;

  cudaFuncSetAttribute(gnn_wmma_kernel,
                       cudaFuncAttributeMaxDynamicSharedMemorySize, SMEM_TOTAL);

  dim3 grid(NT / BN, NB), block(NTHREADS);
  gnn_wmma_kernel<<<grid, block, SMEM_TOTAL>>>(X, X, Ws, Wn, bb, nullptr);
  gnn_wmma_kernel<<<grid, block, SMEM_TOTAL>>>(X, nullptr, Ws + DD * DD,
                                               Wn + DD * DD, bb + DD, out);
}

// round 4
// speedup vs baseline: 3.0045x; 1.1178x over previous
#include <cuda_runtime.h>
#include <cuda_fp16.h>
#include <cstdint>

#define NT 2560
#define DD 32
#define NB 4
#define BN 32
#define BM 128
#define NITER (NT / BM)   // 20
#define NTHREADS 256

// ---- smem byte offsets (main kernel) ----
#define SM_XNH 0
#define SM_XNL 2560
#define SM_BUF 5120
#define OFF_XMH 0
#define OFF_XML 10240
#define OFF_HTH 20480
#define OFF_HTL 29184
#define BUFSZ   37888                 // per pipeline stage
#define SM_W    (SM_BUF + 2 * BUFSZ)  // 80896
#define SM_AGG  SM_BUF                // 16KB agg reuses buf region after loop
#define SMEM_TOTAL (SM_W + 8320)      // 89216

// ---- device globals (allocation-free scratch) ----
__device__ float    g_h1 [NB * NT * DD];
__device__ uint32_t g_xhi[NB * NT * DD / 2];   // X split, fp16x2 [b][row][16]
__device__ uint32_t g_xlo[NB * NT * DD / 2];
__device__ uint32_t g_hthi[NB * DD * NT / 2];  // H^T split, fp16x2 [b][d][1280]
__device__ uint32_t g_htlo[NB * DD * NT / 2];

__device__ __forceinline__ uint32_t smem_u32(const void* p) {
  uint32_t a;
  asm("{ .reg .u64 t; cvta.to.shared.u64 t, %1; cvt.u32.u64 %0, t; }" : "=r"(a) : "l"(p));
  return a;
}
__device__ __forceinline__ void mma16816(float c[4], const uint32_t a[4],
                                         const uint32_t b[2]) {
  asm volatile(
      "mma.sync.aligned.m16n8k16.row.col.f32.f16.f16.f32 "
      "{%0,%1,%2,%3}, {%4,%5,%6,%7}, {%8,%9}, {%0,%1,%2,%3};"
      : "+f"(c[0]), "+f"(c[1]), "+f"(c[2]), "+f"(c[3])
      : "r"(a[0]), "r"(a[1]), "r"(a[2]), "r"(a[3]), "r"(b[0]), "r"(b[1]));
}
__device__ __forceinline__ void cp16(uint32_t dst, const void* src) {
  asm volatile("cp.async.cg.shared.global [%0], [%1], 16;" :: "r"(dst), "l"(src));
}
#define CP_COMMIT() asm volatile("cp.async.commit_group;")
template <int N> __device__ __forceinline__ void cp_wait() {
  asm volatile("cp.async.wait_group %0;" :: "n"(N));
}
__device__ __forceinline__ float tanh_relu(float s) {
  float r = fmaxf(s, 0.0f);
  float e = __expf(-2.0f * r);
  return __fdividef(1.0f - e, 1.0f + e);
}
__device__ __forceinline__ void pack_split(float x, float y,
                                           uint32_t& hi, uint32_t& lo) {
  __half2 h = __floats2half2_rn(x, y);
  float2 hf = __half22float2(h);
  __half2 l = __floats2half2_rn(x - hf.x, y - hf.y);
  hi = *reinterpret_cast<uint32_t*>(&h);
  lo = *reinterpret_cast<uint32_t*>(&l);
}

// ---- prep: split src rows to fp16 hi/lo (optional) + write transposed split ----
__global__ void prep_kernel(const float* __restrict__ src_p, int write_x) {
  __shared__ uint32_t sxh[64][20], sxl[64][20];
  const float* src = src_p ? src_p : (const float*)g_h1;
  const int t = threadIdx.x, b = blockIdx.y, r0 = blockIdx.x * 64;
  {
    const int row = t >> 2, q = t & 3;
    const float4* p = (const float4*)(src + ((size_t)b * NT + r0 + row) * DD + q * 8);
    float4 v0 = p[0], v1 = p[1];
    uint32_t h[4], l[4];
    pack_split(v0.x, v0.y, h[0], l[0]); pack_split(v0.z, v0.w, h[1], l[1]);
    pack_split(v1.x, v1.y, h[2], l[2]); pack_split(v1.z, v1.w, h[3], l[3]);
    uint4 hv = make_uint4(h[0], h[1], h[2], h[3]);
    uint4 lv = make_uint4(l[0], l[1], l[2], l[3]);
    *(uint4*)&sxh[row][q * 4] = hv;
    *(uint4*)&sxl[row][q * 4] = lv;
    if (write_x) {
      size_t xi = ((size_t)b * NT + r0 + row) * 16 + q * 4;
      *(uint4*)&g_xhi[xi] = hv;
      *(uint4*)&g_xlo[xi] = lv;
    }
  }
  __syncthreads();
  {
    const int d = t >> 3;
    const uint32_t sh = (d & 1) * 16;
    const size_t obase = ((size_t)b * DD + d) * (NT / 2) + (r0 >> 1);
    #pragma unroll
    for (int j = 0; j < 4; ++j) {
      const int p = (t & 7) * 4 + j;
      uint32_t h0 = (sxh[2 * p][d >> 1] >> sh) & 0xffffu;
      uint32_t h1 = (sxh[2 * p + 1][d >> 1] >> sh) & 0xffffu;
      uint32_t l0 = (sxl[2 * p][d >> 1] >> sh) & 0xffffu;
      uint32_t l1 = (sxl[2 * p + 1][d >> 1] >> sh) & 0xffffu;
      g_hthi[obase + p] = h0 | (h1 << 16);
      g_htlo[obase + p] = l0 | (l1 << 16);
    }
  }
}

// ---- main fused layer ----
__global__ __launch_bounds__(NTHREADS, 2)
void gnn_main(const float* __restrict__ hin_p,
              const float* __restrict__ Ws, const float* __restrict__ Wn,
              const float* __restrict__ bias, float* __restrict__ hout_p)
{
  extern __shared__ char sm[];
  const uint32_t sb = smem_u32(sm);
  const int t = threadIdx.x, lane = t & 31, wid = t >> 5;
  const int wr = wid >> 2, wc = wid & 3, g = lane >> 2, tig = lane & 3;
  const int bx = blockIdx.x, b = blockIdx.y;
  const int n0 = bx * BN;
  const int mtdiag = bx >> 2, doff = (bx & 3) * 32;

  const float* Hin  = hin_p  ? hin_p  : (const float*)g_h1;
  float*       Hout = hout_p ? hout_p : g_h1;

  // weights -> smem
  float* sW = (float*)(sm + SM_W);
  for (int i = t; i < 2 * DD * DD + DD; i += NTHREADS) {
    float v;
    if (i < 1024)      v = Ws[i];
    else if (i < 2048) v = Wn[i - 1024];
    else               v = bias[i - 2048];
    sW[i] = v;
  }
  // Xn tile (persistent): 32 rows x 64B hi/lo
  {
    const int row = t >> 3, q = t & 7;
    const size_t xi = ((size_t)b * NT + n0 + row) * 16 + q * 2;
    *(uint2*)(sm + SM_XNH + row * 80 + q * 8) = *(const uint2*)(g_xhi + xi);
    *(uint2*)(sm + SM_XNL + row * 80 + q * 8) = *(const uint2*)(g_xlo + xi);
  }

  // tile-issue via cp.async (8x16B per thread)
  auto issue = [&](int mt) {
    const int m0 = mt * BM;
    const uint32_t base = sb + SM_BUF + (uint32_t)(mt & 1) * BUFSZ;
    const size_t xbase = ((size_t)b * NT + m0) * 16;
    const size_t hbase = (size_t)b * DD * (NT / 2) + (m0 >> 1);
    #pragma unroll
    for (int i = 0; i < 2; ++i) {
      const int c = t + i * 256;
      const int row = c >> 2, q = c & 3;
      cp16(base + OFF_XMH + row * 80 + q * 16, g_xhi + xbase + row * 16 + q * 4);
      cp16(base + OFF_XML + row * 80 + q * 16, g_xlo + xbase + row * 16 + q * 4);
      const int d = c >> 4, q2 = c & 15;
      cp16(base + OFF_HTH + d * 272 + q2 * 16, g_hthi + hbase + (size_t)d * (NT / 2) + q2 * 4);
      cp16(base + OFF_HTL + d * 272 + q2 * 16, g_htlo + hbase + (size_t)d * (NT / 2) + q2 * 4);
    }
    CP_COMMIT();
  };

  const int aoff  = (16 * wr + g) * 80 + tig * 4;   // A from Xn
  const int boff1 = (32 * wc + g) * 80 + tig * 4;   // B from Xm
  const int boff2 = g * 272 + 64 * wc + tig * 4;    // B from HT

  float acc2[4][4];
  #pragma unroll
  for (int nc = 0; nc < 4; ++nc)
    #pragma unroll
    for (int e = 0; e < 4; ++e) acc2[nc][e] = 0.0f;

  issue(0);

  for (int mt = 0; mt < NITER; ++mt) {
    if (mt + 1 < NITER) { issue(mt + 1); cp_wait<1>(); }
    else                { cp_wait<0>(); }
    __syncthreads();

    const char* buf = sm + SM_BUF + (size_t)(mt & 1) * BUFSZ;
    const bool diag = (mt == mtdiag);

    // ---- phase 1: S[32x128] chunk per warp ----
    float acc[4][4];
    #pragma unroll
    for (int mc = 0; mc < 4; ++mc)
      #pragma unroll
      for (int e = 0; e < 4; ++e) acc[mc][e] = 0.0f;

    #pragma unroll
    for (int kt = 0; kt < 2; ++kt) {
      uint32_t AH[4], AL[4];
      {
        const char* pH = sm + SM_XNH + aoff + kt * 32;
        AH[0] = *(const uint32_t*)(pH);       AH[1] = *(const uint32_t*)(pH + 640);
        AH[2] = *(const uint32_t*)(pH + 16);  AH[3] = *(const uint32_t*)(pH + 656);
        const char* pL = sm + SM_XNL + aoff + kt * 32;
        AL[0] = *(const uint32_t*)(pL);       AL[1] = *(const uint32_t*)(pL + 640);
        AL[2] = *(const uint32_t*)(pL + 16);  AL[3] = *(const uint32_t*)(pL + 656);
      }
      uint32_t BH[4][2], BL[4][2];
      #pragma unroll
      for (int mc = 0; mc < 4; ++mc) {
        const char* pH = buf + OFF_XMH + boff1 + mc * 640 + kt * 32;
        BH[mc][0] = *(const uint32_t*)(pH);
        BH[mc][1] = *(const uint32_t*)(pH + 16);
        const char* pL = buf + OFF_XML + boff1 + mc * 640 + kt * 32;
        BL[mc][0] = *(const uint32_t*)(pL);
        BL[mc][1] = *(const uint32_t*)(pL + 16);
      }
      #pragma unroll
      for (int mc = 0; mc < 4; ++mc) {
        mma16816(acc[mc], AH, BH[mc]);
        mma16816(acc[mc], AH, BL[mc]);
        mma16816(acc[mc], AL, BH[mc]);
      }
    }

    // ---- nonlinearity + self-loop; C -> phase-2 A frags in registers ----
    uint32_t sA2H[8], sA2L[8];
    #pragma unroll
    for (int mc = 0; mc < 4; ++mc) {
      float v0 = tanh_relu(acc[mc][0]);
      float v1 = tanh_relu(acc[mc][1]);
      float v2 = tanh_relu(acc[mc][2]);
      float v3 = tanh_relu(acc[mc][3]);
      if (diag) {
        const int nl = 16 * wr + g;
        const int ml = 32 * wc + 8 * mc + 2 * tig;
        if (ml     == nl + doff)     v0 += 0.5f;
        if (ml + 1 == nl + doff)     v1 += 0.5f;
        if (ml     == nl + 8 + doff) v2 += 0.5f;
        if (ml + 1 == nl + 8 + doff) v3 += 0.5f;
      }
      pack_split(v0, v1, sA2H[2 * mc],     sA2L[2 * mc]);
      pack_split(v2, v3, sA2H[2 * mc + 1], sA2L[2 * mc + 1]);
    }

    // ---- phase 2: agg += S x H (K split across warps by m-slice) ----
    #pragma unroll
    for (int kt = 0; kt < 2; ++kt) {
      uint32_t BH[4][2], BL[4][2];
      #pragma unroll
      for (int nc = 0; nc < 4; ++nc) {
        const char* pH = buf + OFF_HTH + boff2 + nc * 2176 + kt * 32;
        BH[nc][0] = *(const uint32_t*)(pH);
        BH[nc][1] = *(const uint32_t*)(pH + 16);
        const char* pL = buf + OFF_HTL + boff2 + nc * 2176 + kt * 32;
        BL[nc][0] = *(const uint32_t*)(pL);
        BL[nc][1] = *(const uint32_t*)(pL + 16);
      }
      #pragma unroll
      for (int nc = 0; nc < 4; ++nc) {
        mma16816(acc2[nc], &sA2H[4 * kt], BH[nc]);
        mma16816(acc2[nc], &sA2H[4 * kt], BL[nc]);
        mma16816(acc2[nc], &sA2L[4 * kt], BH[nc]);
      }
    }
    __syncthreads();
  }

  // ---- cross-warp reduction of agg (4 m-slices) ----
  float* aggbuf = (float*)(sm + SM_AGG);
  {
    float* p = aggbuf + wc * 1024;
    const int nl = 16 * wr + g;
    #pragma unroll
    for (int nc = 0; nc < 4; ++nc) {
      const int d0 = 8 * nc + 2 * tig;
      p[nl * 32 + d0]           = acc2[nc][0];
      p[nl * 32 + d0 + 1]       = acc2[nc][1];
      p[(nl + 8) * 32 + d0]     = acc2[nc][2];
      p[(nl + 8) * 32 + d0 + 1] = acc2[nc][3];
    }
  }
  __syncthreads();
  {
    float4* a4 = (float4*)aggbuf;
    float4 s = a4[t], s1 = a4[t + 256], s2 = a4[t + 512], s3 = a4[t + 768];
    a4[t] = make_float4(s.x + s1.x + s2.x + s3.x, s.y + s1.y + s2.y + s3.y,
                        s.z + s1.z + s2.z + s3.z, s.w + s1.w + s2.w + s3.w);
  }
  __syncthreads();

  // ---- epilogue: out = elu(h*Ws + agg*Wn + b) ----
  {
    const int r = t >> 3, e0 = (t & 7) * 4;
    float h[DD];
    const float4* hr = (const float4*)(Hin + ((size_t)b * NT + n0 + r) * DD);
    #pragma unroll
    for (int q = 0; q < 8; ++q) {
      float4 v = hr[q];
      h[4 * q] = v.x; h[4 * q + 1] = v.y; h[4 * q + 2] = v.z; h[4 * q + 3] = v.w;
    }
    float out[4];
    #pragma unroll
    for (int e = 0; e < 4; ++e) out[e] = sW[2048 + e0 + e];
    const float* ag = aggbuf + r * DD;
    #pragma unroll
    for (int d = 0; d < DD; ++d) {
      const float hd = h[d];
      const float ad = ag[d];
      const float* ws = sW + d * DD + e0;
      const float* wn = sW + 1024 + d * DD + e0;
      #pragma unroll
      for (int e = 0; e < 4; ++e) out[e] += hd * ws[e] + ad * wn[e];
    }
    #pragma unroll
    for (int e = 0; e < 4; ++e) {
      float v = out[e];
      out[e] = v > 0.0f ? v : (__expf(v) - 1.0f);
    }
    *(float4*)(Hout + ((size_t)b * NT + n0 + r) * DD + e0) =
        make_float4(out[0], out[1], out[2], out[3]);
  }
}

extern "C" void kernel_launch(void* const* d_in, const int* in_sizes, int n_in,
                              void* d_out, int out_size) {
  (void)in_sizes; (void)n_in; (void)out_size;
  const float* X  = (const float*)d_in[0];
  const float* Ws = (const float*)d_in[1];   // [2,32,32]
  const float* Wn = (const float*)d_in[2];   // [2,32,32]
  const float* bb = (const float*)d_in[3];   // [2,32]
  float* out = (float*)d_out;

  cudaFuncSetAttribute(gnn_main,
                       cudaFuncAttributeMaxDynamicSharedMemorySize, SMEM_TOTAL);

  dim3 pgrid(NT / 64, NB), pblk(256);
  dim3 grid(NT / BN, NB), blk(NTHREADS);

  prep_kernel<<<pgrid, pblk>>>(X, 1);                 // g_x*, g_ht* (H = X)
  gnn_main<<<grid, blk, SMEM_TOTAL>>>(X, Ws, Wn, bb, nullptr);          // -> g_h1
  prep_kernel<<<pgrid, pblk>>>(nullptr, 0);           // g_ht* from g_h1
  gnn_main<<<grid, blk, SMEM_TOTAL>>>(nullptr, Ws + 1024, Wn + 1024, bb + 32, out);
}

// round 5
// speedup vs baseline: 3.7129x; 1.2358x over previous
#include <cuda_runtime.h>
#include <cuda_fp16.h>
#include <cstdint>

#define NT 2560
#define DD 32
#define NB 4
#define BN 32
#define BM 128
#define NITER (NT / BM)   // 20
#define NTHREADS 256

// ---- smem byte offsets (main kernel) ----
#define SM_XNH 0
#define SM_XNL 2560
#define SM_BUF 5120
#define OFF_XMH 0
#define OFF_XML 10240
#define OFF_HTH 20480
#define BUFSZ   29184                 // per pipeline stage (XM hi/lo + HT hi)
#define SM_W    (SM_BUF + 2 * BUFSZ)  // 63488
#define SM_AGG  SM_BUF                // 16KB agg reuses buf region after loop
#define SMEM_TOTAL (SM_W + 8320)      // 71808  -> 3 CTAs/SM

// ---- device globals (allocation-free scratch) ----
__device__ float    g_h1 [NB * NT * DD];
__device__ uint32_t g_xhi[NB * NT * DD / 2];   // X split, fp16x2 [b][row][16]
__device__ uint32_t g_xlo[NB * NT * DD / 2];
__device__ uint32_t g_hthi[NB * DD * NT / 2];  // H^T hi, fp16x2 [b][d][1280]

__device__ __forceinline__ uint32_t smem_u32(const void* p) {
  uint32_t a;
  asm("{ .reg .u64 t; cvta.to.shared.u64 t, %1; cvt.u32.u64 %0, t; }" : "=r"(a) : "l"(p));
  return a;
}
__device__ __forceinline__ void mma16816(float c[4], const uint32_t a[4],
                                         const uint32_t b[2]) {
  asm volatile(
      "mma.sync.aligned.m16n8k16.row.col.f32.f16.f16.f32 "
      "{%0,%1,%2,%3}, {%4,%5,%6,%7}, {%8,%9}, {%0,%1,%2,%3};"
      : "+f"(c[0]), "+f"(c[1]), "+f"(c[2]), "+f"(c[3])
      : "r"(a[0]), "r"(a[1]), "r"(a[2]), "r"(a[3]), "r"(b[0]), "r"(b[1]));
}
__device__ __forceinline__ void cp16(uint32_t dst, const void* src) {
  asm volatile("cp.async.cg.shared.global [%0], [%1], 16;" :: "r"(dst), "l"(src));
}
#define CP_COMMIT() asm volatile("cp.async.commit_group;")
template <int N> __device__ __forceinline__ void cp_wait() {
  asm volatile("cp.async.wait_group %0;" :: "n"(N));
}
__device__ __forceinline__ float tanh_relu(float s) {
  float r = fmaxf(s, 0.0f);
  float e = __expf(-2.0f * r);
  return __fdividef(1.0f - e, 1.0f + e);
}
__device__ __forceinline__ void pack_split(float x, float y,
                                           uint32_t& hi, uint32_t& lo) {
  __half2 h = __floats2half2_rn(x, y);
  float2 hf = __half22float2(h);
  __half2 l = __floats2half2_rn(x - hf.x, y - hf.y);
  hi = *reinterpret_cast<uint32_t*>(&h);
  lo = *reinterpret_cast<uint32_t*>(&l);
}

// ---- prep: split src rows to fp16 hi/lo (optional) + write transposed hi ----
__global__ void prep_kernel(const float* __restrict__ src_p, int write_x) {
  __shared__ uint32_t sxh[64][20];
  const float* src = src_p ? src_p : (const float*)g_h1;
  const int t = threadIdx.x, b = blockIdx.y, r0 = blockIdx.x * 64;
  {
    const int row = t >> 2, q = t & 3;
    const float4* p = (const float4*)(src + ((size_t)b * NT + r0 + row) * DD + q * 8);
    float4 v0 = p[0], v1 = p[1];
    uint32_t h[4], l[4];
    pack_split(v0.x, v0.y, h[0], l[0]); pack_split(v0.z, v0.w, h[1], l[1]);
    pack_split(v1.x, v1.y, h[2], l[2]); pack_split(v1.z, v1.w, h[3], l[3]);
    uint4 hv = make_uint4(h[0], h[1], h[2], h[3]);
    *(uint4*)&sxh[row][q * 4] = hv;
    if (write_x) {
      size_t xi = ((size_t)b * NT + r0 + row) * 16 + q * 4;
      *(uint4*)&g_xhi[xi] = hv;
      *(uint4*)&g_xlo[xi] = make_uint4(l[0], l[1], l[2], l[3]);
    }
  }
  __syncthreads();
  {
    const int d = t >> 3;
    const uint32_t sh = (d & 1) * 16;
    const size_t obase = ((size_t)b * DD + d) * (NT / 2) + (r0 >> 1);
    #pragma unroll
    for (int j = 0; j < 4; ++j) {
      const int p = (t & 7) * 4 + j;
      uint32_t h0 = (sxh[2 * p][d >> 1] >> sh) & 0xffffu;
      uint32_t h1 = (sxh[2 * p + 1][d >> 1] >> sh) & 0xffffu;
      g_hthi[obase + p] = h0 | (h1 << 16);
    }
  }
}

// ---- main fused layer ----
__global__ __launch_bounds__(NTHREADS, 3)
void gnn_main(const float* __restrict__ hin_p,
              const float* __restrict__ Ws, const float* __restrict__ Wn,
              const float* __restrict__ bias, float* __restrict__ hout_p)
{
  extern __shared__ char sm[];
  const uint32_t sb = smem_u32(sm);
  const int t = threadIdx.x, lane = t & 31, wid = t >> 5;
  const int wr = wid >> 2, wc = wid & 3, g = lane >> 2, tig = lane & 3;
  const int bx = blockIdx.x, b = blockIdx.y;
  const int n0 = bx * BN;
  const int mtdiag = bx >> 2, doff = (bx & 3) * 32;

  const float* Hin  = hin_p  ? hin_p  : (const float*)g_h1;
  float*       Hout = hout_p ? hout_p : g_h1;

  // weights -> smem
  float* sW = (float*)(sm + SM_W);
  for (int i = t; i < 2 * DD * DD + DD; i += NTHREADS) {
    float v;
    if (i < 1024)      v = Ws[i];
    else if (i < 2048) v = Wn[i - 1024];
    else               v = bias[i - 2048];
    sW[i] = v;
  }
  // Xn tile (persistent): 32 rows x 64B hi/lo
  {
    const int row = t >> 3, q = t & 7;
    const size_t xi = ((size_t)b * NT + n0 + row) * 16 + q * 2;
    *(uint2*)(sm + SM_XNH + row * 80 + q * 8) = *(const uint2*)(g_xhi + xi);
    *(uint2*)(sm + SM_XNL + row * 80 + q * 8) = *(const uint2*)(g_xlo + xi);
  }

  // tile-issue via cp.async (6x16B per thread)
  auto issue = [&](int mt) {
    const int m0 = mt * BM;
    const uint32_t base = sb + SM_BUF + (uint32_t)(mt & 1) * BUFSZ;
    const size_t xbase = ((size_t)b * NT + m0) * 16;
    const size_t hbase = (size_t)b * DD * (NT / 2) + (m0 >> 1);
    #pragma unroll
    for (int i = 0; i < 2; ++i) {
      const int c = t + i * 256;
      const int row = c >> 2, q = c & 3;
      cp16(base + OFF_XMH + row * 80 + q * 16, g_xhi + xbase + row * 16 + q * 4);
      cp16(base + OFF_XML + row * 80 + q * 16, g_xlo + xbase + row * 16 + q * 4);
      const int d = c >> 4, q2 = c & 15;
      cp16(base + OFF_HTH + d * 272 + q2 * 16, g_hthi + hbase + (size_t)d * (NT / 2) + q2 * 4);
    }
    CP_COMMIT();
  };

  const int aoff  = (16 * wr + g) * 80 + tig * 4;   // A from Xn
  const int boff1 = (32 * wc + g) * 80 + tig * 4;   // B from Xm
  const int boff2 = g * 272 + 64 * wc + tig * 4;    // B from HT

  float acc2[4][4];
  #pragma unroll
  for (int nc = 0; nc < 4; ++nc)
    #pragma unroll
    for (int e = 0; e < 4; ++e) acc2[nc][e] = 0.0f;

  issue(0);

  for (int mt = 0; mt < NITER; ++mt) {
    if (mt + 1 < NITER) { issue(mt + 1); cp_wait<1>(); }
    else                { cp_wait<0>(); }
    __syncthreads();

    const char* buf = sm + SM_BUF + (size_t)(mt & 1) * BUFSZ;
    const bool diag = (mt == mtdiag);

    // ---- phase 1: S[32x128] chunk per warp (3-pass hi/lo split) ----
    float acc[4][4];
    #pragma unroll
    for (int mc = 0; mc < 4; ++mc)
      #pragma unroll
      for (int e = 0; e < 4; ++e) acc[mc][e] = 0.0f;

    #pragma unroll
    for (int kt = 0; kt < 2; ++kt) {
      uint32_t AH[4], AL[4];
      {
        const char* pH = sm + SM_XNH + aoff + kt * 32;
        AH[0] = *(const uint32_t*)(pH);       AH[1] = *(const uint32_t*)(pH + 640);
        AH[2] = *(const uint32_t*)(pH + 16);  AH[3] = *(const uint32_t*)(pH + 656);
        const char* pL = sm + SM_XNL + aoff + kt * 32;
        AL[0] = *(const uint32_t*)(pL);       AL[1] = *(const uint32_t*)(pL + 640);
        AL[2] = *(const uint32_t*)(pL + 16);  AL[3] = *(const uint32_t*)(pL + 656);
      }
      uint32_t BH[4][2], BL[4][2];
      #pragma unroll
      for (int mc = 0; mc < 4; ++mc) {
        const char* pH = buf + OFF_XMH + boff1 + mc * 640 + kt * 32;
        BH[mc][0] = *(const uint32_t*)(pH);
        BH[mc][1] = *(const uint32_t*)(pH + 16);
        const char* pL = buf + OFF_XML + boff1 + mc * 640 + kt * 32;
        BL[mc][0] = *(const uint32_t*)(pL);
        BL[mc][1] = *(const uint32_t*)(pL + 16);
      }
      #pragma unroll
      for (int mc = 0; mc < 4; ++mc) {
        mma16816(acc[mc], AH, BH[mc]);
        mma16816(acc[mc], AH, BL[mc]);
        mma16816(acc[mc], AL, BH[mc]);
      }
    }

    // ---- nonlinearity + self-loop; C -> phase-2 A frags in registers ----
    uint32_t sA2H[8], sA2L[8];
    #pragma unroll
    for (int mc = 0; mc < 4; ++mc) {
      float v0 = tanh_relu(acc[mc][0]);
      float v1 = tanh_relu(acc[mc][1]);
      float v2 = tanh_relu(acc[mc][2]);
      float v3 = tanh_relu(acc[mc][3]);
      if (diag) {
        const int nl = 16 * wr + g;
        const int ml = 32 * wc + 8 * mc + 2 * tig;
        if (ml     == nl + doff)     v0 += 0.5f;
        if (ml + 1 == nl + doff)     v1 += 0.5f;
        if (ml     == nl + 8 + doff) v2 += 0.5f;
        if (ml + 1 == nl + 8 + doff) v3 += 0.5f;
      }
      pack_split(v0, v1, sA2H[2 * mc],     sA2L[2 * mc]);
      pack_split(v2, v3, sA2H[2 * mc + 1], sA2L[2 * mc + 1]);
    }

    // ---- phase 2: agg += (S_hi + S_lo) x H_hi ----
    #pragma unroll
    for (int kt = 0; kt < 2; ++kt) {
      uint32_t BH[4][2];
      #pragma unroll
      for (int nc = 0; nc < 4; ++nc) {
        const char* pH = buf + OFF_HTH + boff2 + nc * 2176 + kt * 32;
        BH[nc][0] = *(const uint32_t*)(pH);
        BH[nc][1] = *(const uint32_t*)(pH + 16);
      }
      #pragma unroll
      for (int nc = 0; nc < 4; ++nc) {
        mma16816(acc2[nc], &sA2H[4 * kt], BH[nc]);
        mma16816(acc2[nc], &sA2L[4 * kt], BH[nc]);
      }
    }
    __syncthreads();
  }

  // ---- cross-warp reduction of agg (4 m-slices) ----
  float* aggbuf = (float*)(sm + SM_AGG);
  {
    float* p = aggbuf + wc * 1024;
    const int nl = 16 * wr + g;
    #pragma unroll
    for (int nc = 0; nc < 4; ++nc) {
      const int d0 = 8 * nc + 2 * tig;
      p[nl * 32 + d0]           = acc2[nc][0];
      p[nl * 32 + d0 + 1]       = acc2[nc][1];
      p[(nl + 8) * 32 + d0]     = acc2[nc][2];
      p[(nl + 8) * 32 + d0 + 1] = acc2[nc][3];
    }
  }
  __syncthreads();
  {
    float4* a4 = (float4*)aggbuf;
    float4 s = a4[t], s1 = a4[t + 256], s2 = a4[t + 512], s3 = a4[t + 768];
    a4[t] = make_float4(s.x + s1.x + s2.x + s3.x, s.y + s1.y + s2.y + s3.y,
                        s.z + s1.z + s2.z + s3.z, s.w + s1.w + s2.w + s3.w);
  }
  __syncthreads();

  // ---- epilogue: out = elu(h*Ws + agg*Wn + b) ----
  {
    const int r = t >> 3, e0 = (t & 7) * 4;
    float h[DD];
    const float4* hr = (const float4*)(Hin + ((size_t)b * NT + n0 + r) * DD);
    #pragma unroll
    for (int q = 0; q < 8; ++q) {
      float4 v = hr[q];
      h[4 * q] = v.x; h[4 * q + 1] = v.y; h[4 * q + 2] = v.z; h[4 * q + 3] = v.w;
    }
    float out[4];
    #pragma unroll
    for (int e = 0; e < 4; ++e) out[e] = sW[2048 + e0 + e];
    const float* ag = aggbuf + r * DD;
    #pragma unroll
    for (int d = 0; d < DD; ++d) {
      const float hd = h[d];
      const float ad = ag[d];
      const float* ws = sW + d * DD + e0;
      const float* wn = sW + 1024 + d * DD + e0;
      #pragma unroll
      for (int e = 0; e < 4; ++e) out[e] += hd * ws[e] + ad * wn[e];
    }
    #pragma unroll
    for (int e = 0; e < 4; ++e) {
      float v = out[e];
      out[e] = v > 0.0f ? v : (__expf(v) - 1.0f);
    }
    *(float4*)(Hout + ((size_t)b * NT + n0 + r) * DD + e0) =
        make_float4(out[0], out[1], out[2], out[3]);
  }
}

extern "C" void kernel_launch(void* const* d_in, const int* in_sizes, int n_in,
                              void* d_out, int out_size) {
  (void)in_sizes; (void)n_in; (void)out_size;
  const float* X  = (const float*)d_in[0];
  const float* Ws = (const float*)d_in[1];   // [2,32,32]
  const float* Wn = (const float*)d_in[2];   // [2,32,32]
  const float* bb = (const float*)d_in[3];   // [2,32]
  float* out = (float*)d_out;

  cudaFuncSetAttribute(gnn_main,
                       cudaFuncAttributeMaxDynamicSharedMemorySize, SMEM_TOTAL);

  dim3 pgrid(NT / 64, NB), pblk(256);
  dim3 grid(NT / BN, NB), blk(NTHREADS);

  prep_kernel<<<pgrid, pblk>>>(X, 1);                 // g_x*, g_hthi (H = X)
  gnn_main<<<grid, blk, SMEM_TOTAL>>>(X, Ws, Wn, bb, nullptr);          // -> g_h1
  prep_kernel<<<pgrid, pblk>>>(nullptr, 0);           // g_hthi from g_h1
  gnn_main<<<grid, blk, SMEM_TOTAL>>>(nullptr, Ws + 1024, Wn + 1024, bb + 32, out);
}

// round 6
// speedup vs baseline: 5.1287x; 1.3813x over previous
#include <cuda_runtime.h>
#include <cuda_fp16.h>
#include <cstdint>

#define NT 2560
#define DD 32
#define NB 4
#define BN 32
#define BM 128
#define NITER (NT / BM)   // 20
#define NTHREADS 256

// ---- smem byte offsets (main kernel) ----
#define SM_XNH 0
#define SM_XNL 2560
#define SM_BUF 5120
#define OFF_XMH 0
#define OFF_XML 10240
#define OFF_HTH 20480
#define BUFSZ   29184                 // per pipeline stage (XM hi/lo + HT hi)
#define SM_W    (SM_BUF + 2 * BUFSZ)  // 63488
#define SM_AGG  SM_BUF                // agg reuses buf region after loop
#define SMEM_TOTAL (SM_W + 8320)      // 71808

// ---- device globals (allocation-free scratch) ----
__device__ float    g_h1 [NB * NT * DD];
__device__ uint32_t g_xhi[NB * NT * DD / 2];   // X split, fp16x2 [b][row][16]
__device__ uint32_t g_xlo[NB * NT * DD / 2];
__device__ uint32_t g_hthi[NB * DD * NT / 2];  // H^T hi, fp16x2 [b][d][1280]

__device__ __forceinline__ uint32_t smem_u32(const void* p) {
  uint32_t a;
  asm("{ .reg .u64 t; cvta.to.shared.u64 t, %1; cvt.u32.u64 %0, t; }" : "=r"(a) : "l"(p));
  return a;
}
__device__ __forceinline__ void mma16816(float c[4], const uint32_t a[4],
                                         const uint32_t b[2]) {
  asm volatile(
      "mma.sync.aligned.m16n8k16.row.col.f32.f16.f16.f32 "
      "{%0,%1,%2,%3}, {%4,%5,%6,%7}, {%8,%9}, {%0,%1,%2,%3};"
      : "+f"(c[0]), "+f"(c[1]), "+f"(c[2]), "+f"(c[3])
      : "r"(a[0]), "r"(a[1]), "r"(a[2]), "r"(a[3]), "r"(b[0]), "r"(b[1]));
}
__device__ __forceinline__ void ldsm4(uint32_t r[4], uint32_t addr) {
  asm volatile("ldmatrix.sync.aligned.m8n8.x4.shared.b16 {%0,%1,%2,%3}, [%4];"
               : "=r"(r[0]), "=r"(r[1]), "=r"(r[2]), "=r"(r[3]) : "r"(addr));
}
__device__ __forceinline__ void cp16(uint32_t dst, const void* src) {
  asm volatile("cp.async.cg.shared.global [%0], [%1], 16;" :: "r"(dst), "l"(src));
}
#define CP_COMMIT() asm volatile("cp.async.commit_group;")
template <int N> __device__ __forceinline__ void cp_wait() {
  asm volatile("cp.async.wait_group %0;" :: "n"(N));
}
__device__ __forceinline__ float tanh_relu(float s) {
  float r = fmaxf(s, 0.0f), v;
  asm("tanh.approx.f32 %0, %1;" : "=f"(v) : "f"(r));
  return v;
}
__device__ __forceinline__ uint32_t pack_h2(float x, float y) {
  __half2 h = __floats2half2_rn(x, y);
  return *reinterpret_cast<uint32_t*>(&h);
}
__device__ __forceinline__ void pack_split(float x, float y,
                                           uint32_t& hi, uint32_t& lo) {
  __half2 h = __floats2half2_rn(x, y);
  float2 hf = __half22float2(h);
  __half2 l = __floats2half2_rn(x - hf.x, y - hf.y);
  hi = *reinterpret_cast<uint32_t*>(&h);
  lo = *reinterpret_cast<uint32_t*>(&l);
}

// ---- prep: split src rows to fp16 hi/lo (optional) + write transposed hi ----
__global__ void prep_kernel(const float* __restrict__ src_p, int write_x) {
  __shared__ uint32_t sxh[64][20];
  const float* src = src_p ? src_p : (const float*)g_h1;
  const int t = threadIdx.x, b = blockIdx.y, r0 = blockIdx.x * 64;
  {
    const int row = t >> 2, q = t & 3;
    const float4* p = (const float4*)(src + ((size_t)b * NT + r0 + row) * DD + q * 8);
    float4 v0 = p[0], v1 = p[1];
    uint32_t h[4], l[4];
    pack_split(v0.x, v0.y, h[0], l[0]); pack_split(v0.z, v0.w, h[1], l[1]);
    pack_split(v1.x, v1.y, h[2], l[2]); pack_split(v1.z, v1.w, h[3], l[3]);
    uint4 hv = make_uint4(h[0], h[1], h[2], h[3]);
    *(uint4*)&sxh[row][q * 4] = hv;
    if (write_x) {
      size_t xi = ((size_t)b * NT + r0 + row) * 16 + q * 4;
      *(uint4*)&g_xhi[xi] = hv;
      *(uint4*)&g_xlo[xi] = make_uint4(l[0], l[1], l[2], l[3]);
    }
  }
  __syncthreads();
  {
    const int d = t >> 3;
    const uint32_t sh = (d & 1) * 16;
    const size_t obase = ((size_t)b * DD + d) * (NT / 2) + (r0 >> 1);
    #pragma unroll
    for (int j = 0; j < 4; ++j) {
      const int p = (t & 7) * 4 + j;
      uint32_t h0 = (sxh[2 * p][d >> 1] >> sh) & 0xffffu;
      uint32_t h1 = (sxh[2 * p + 1][d >> 1] >> sh) & 0xffffu;
      g_hthi[obase + p] = h0 | (h1 << 16);
    }
  }
}

// ---- main fused layer ----
__global__ __launch_bounds__(NTHREADS, 3)
void gnn_main(const float* __restrict__ hin_p,
              const float* __restrict__ Ws, const float* __restrict__ Wn,
              const float* __restrict__ bias, float* __restrict__ hout_p)
{
  extern __shared__ char sm[];
  const uint32_t sb = smem_u32(sm);
  const int t = threadIdx.x, lane = t & 31, wid = t >> 5;
  const int wr = wid >> 2, wc = wid & 3, g = lane >> 2, tig = lane & 3;
  const int bx = blockIdx.x, b = blockIdx.y;
  const int n0 = bx * BN;
  const int mtdiag = bx >> 2, doff = (bx & 3) * 32;

  const float* Hin  = hin_p  ? hin_p  : (const float*)g_h1;
  float*       Hout = hout_p ? hout_p : g_h1;

  // weights -> smem
  float* sW = (float*)(sm + SM_W);
  for (int i = t; i < 2 * DD * DD + DD; i += NTHREADS) {
    float v;
    if (i < 1024)      v = Ws[i];
    else if (i < 2048) v = Wn[i - 1024];
    else               v = bias[i - 2048];
    sW[i] = v;
  }
  // Xn tile (persistent): 32 rows x 64B hi/lo
  {
    const int row = t >> 3, q = t & 7;
    const size_t xi = ((size_t)b * NT + n0 + row) * 16 + q * 2;
    *(uint2*)(sm + SM_XNH + row * 80 + q * 8) = *(const uint2*)(g_xhi + xi);
    *(uint2*)(sm + SM_XNL + row * 80 + q * 8) = *(const uint2*)(g_xlo + xi);
  }

  // tile-issue via cp.async (6x16B per thread)
  auto issue = [&](int mt) {
    const int m0 = mt * BM;
    const uint32_t base = sb + SM_BUF + (uint32_t)(mt & 1) * BUFSZ;
    const size_t xbase = ((size_t)b * NT + m0) * 16;
    const size_t hbase = (size_t)b * DD * (NT / 2) + (m0 >> 1);
    #pragma unroll
    for (int i = 0; i < 2; ++i) {
      const int c = t + i * 256;
      const int row = c >> 2, q = c & 3;
      cp16(base + OFF_XMH + row * 80 + q * 16, g_xhi + xbase + row * 16 + q * 4);
      cp16(base + OFF_XML + row * 80 + q * 16, g_xlo + xbase + row * 16 + q * 4);
      const int d = c >> 4, q2 = c & 15;
      cp16(base + OFF_HTH + d * 272 + q2 * 16, g_hthi + hbase + (size_t)d * (NT / 2) + q2 * 4);
    }
    CP_COMMIT();
  };

  // ---- ldmatrix lane addresses ----
  // A (Xn): row = 16*wr + 8*((lane>>3)&1) + (lane&7), col16 = (lane>>4)*16
  const uint32_t a_addr = sb + SM_XNH +
      (uint32_t)(16 * wr + 8 * ((lane >> 3) & 1) + (lane & 7)) * 80u +
      (uint32_t)(lane >> 4) * 16u;
  // B1 (Xm): pair p covers mc=2p,2p+1: row = 32*wc + 16*p + 8*(lane>>4) + (lane&7),
  //          col16 = ((lane>>3)&1)*16 (+kt*32)
  const uint32_t b1_addr = OFF_XMH +
      (uint32_t)(32 * wc + 8 * (lane >> 4) + (lane & 7)) * 80u +
      (uint32_t)((lane >> 3) & 1) * 16u;
  // B2 (HT): pair p covers nc=2p,2p+1: row_d = 16*p + 8*(lane>>4) + (lane&7),
  //          col = 64*wc + kt*32 + ((lane>>3)&1)*16
  const uint32_t b2_addr = OFF_HTH +
      (uint32_t)(8 * (lane >> 4) + (lane & 7)) * 272u +
      (uint32_t)(64 * wc) + (uint32_t)((lane >> 3) & 1) * 16u;

  float acc2[4][4];
  #pragma unroll
  for (int nc = 0; nc < 4; ++nc)
    #pragma unroll
    for (int e = 0; e < 4; ++e) acc2[nc][e] = 0.0f;

  issue(0);
  __syncthreads();                       // Xn tile + weights visible

  // ---- hoisted loop-invariant A fragments (Xn) ----
  uint32_t AH[2][4], AL[2][4];
  #pragma unroll
  for (int kt = 0; kt < 2; ++kt) {
    ldsm4(AH[kt], a_addr + kt * 32);
    ldsm4(AL[kt], a_addr + kt * 32 + 2560);
  }

  for (int mt = 0; mt < NITER; ++mt) {
    if (mt + 1 < NITER) { issue(mt + 1); cp_wait<1>(); }
    else                { cp_wait<0>(); }
    __syncthreads();

    const uint32_t buf = sb + SM_BUF + (uint32_t)(mt & 1) * BUFSZ;
    const bool diag = (mt == mtdiag);

    // ---- phase 1: S[32x128] chunk per warp (3-pass hi/lo split) ----
    float acc[4][4];
    #pragma unroll
    for (int mc = 0; mc < 4; ++mc)
      #pragma unroll
      for (int e = 0; e < 4; ++e) acc[mc][e] = 0.0f;

    #pragma unroll
    for (int kt = 0; kt < 2; ++kt) {
      uint32_t BH[2][4], BL[2][4];   // [pair][r0=b0(mc even),r1=b1,r2=b0(odd),r3=b1]
      #pragma unroll
      for (int p = 0; p < 2; ++p) {
        ldsm4(BH[p], buf + b1_addr + p * 1280u + kt * 32u);
        ldsm4(BL[p], buf + b1_addr + p * 1280u + kt * 32u + 10240u);
      }
      #pragma unroll
      for (int mc = 0; mc < 4; ++mc) {
        const uint32_t* bh = &BH[mc >> 1][(mc & 1) * 2];
        const uint32_t* bl = &BL[mc >> 1][(mc & 1) * 2];
        mma16816(acc[mc], AH[kt], bh);
        mma16816(acc[mc], AH[kt], bl);
        mma16816(acc[mc], AL[kt], bh);
      }
    }

    // ---- nonlinearity + self-loop; C -> phase-2 A frags (fp16 hi only) ----
    uint32_t sA2[8];
    #pragma unroll
    for (int mc = 0; mc < 4; ++mc) {
      float v0 = tanh_relu(acc[mc][0]);
      float v1 = tanh_relu(acc[mc][1]);
      float v2 = tanh_relu(acc[mc][2]);
      float v3 = tanh_relu(acc[mc][3]);
      if (diag) {
        const int nl = 16 * wr + g;
        const int ml = 32 * wc + 8 * mc + 2 * tig;
        if (ml     == nl + doff)     v0 += 0.5f;
        if (ml + 1 == nl + doff)     v1 += 0.5f;
        if (ml     == nl + 8 + doff) v2 += 0.5f;
        if (ml + 1 == nl + 8 + doff) v3 += 0.5f;
      }
      sA2[2 * mc]     = pack_h2(v0, v1);
      sA2[2 * mc + 1] = pack_h2(v2, v3);
    }

    // ---- phase 2: agg += S_hi x H_hi ----
    #pragma unroll
    for (int kt = 0; kt < 2; ++kt) {
      uint32_t BH2[2][4];
      #pragma unroll
      for (int p = 0; p < 2; ++p)
        ldsm4(BH2[p], buf + b2_addr + p * 4352u + kt * 32u);
      #pragma unroll
      for (int nc = 0; nc < 4; ++nc)
        mma16816(acc2[nc], &sA2[4 * kt], &BH2[nc >> 1][(nc & 1) * 2]);
    }
    __syncthreads();
  }

  // ---- cross-warp reduction of agg (4 m-slices) ----
  float* aggbuf = (float*)(sm + SM_AGG);
  {
    float* p = aggbuf + wc * 1024;
    const int nl = 16 * wr + g;
    #pragma unroll
    for (int nc = 0; nc < 4; ++nc) {
      const int d0 = 8 * nc + 2 * tig;
      p[nl * 32 + d0]           = acc2[nc][0];
      p[nl * 32 + d0 + 1]       = acc2[nc][1];
      p[(nl + 8) * 32 + d0]     = acc2[nc][2];
      p[(nl + 8) * 32 + d0 + 1] = acc2[nc][3];
    }
  }
  __syncthreads();
  {
    float4* a4 = (float4*)aggbuf;
    float4 s = a4[t], s1 = a4[t + 256], s2 = a4[t + 512], s3 = a4[t + 768];
    a4[t] = make_float4(s.x + s1.x + s2.x + s3.x, s.y + s1.y + s2.y + s3.y,
                        s.z + s1.z + s2.z + s3.z, s.w + s1.w + s2.w + s3.w);
  }
  __syncthreads();

  // ---- epilogue: out = elu(h*Ws + agg*Wn + b) ----
  {
    const int r = t >> 3, e0 = (t & 7) * 4;
    float h[DD];
    const float4* hr = (const float4*)(Hin + ((size_t)b * NT + n0 + r) * DD);
    #pragma unroll
    for (int q = 0; q < 8; ++q) {
      float4 v = hr[q];
      h[4 * q] = v.x; h[4 * q + 1] = v.y; h[4 * q + 2] = v.z; h[4 * q + 3] = v.w;
    }
    float out[4];
    #pragma unroll
    for (int e = 0; e < 4; ++e) out[e] = sW[2048 + e0 + e];
    const float* ag = aggbuf + r * DD;
    #pragma unroll
    for (int d = 0; d < DD; ++d) {
      const float hd = h[d];
      const float ad = ag[d];
      const float* ws = sW + d * DD + e0;
      const float* wn = sW + 1024 + d * DD + e0;
      #pragma unroll
      for (int e = 0; e < 4; ++e) out[e] += hd * ws[e] + ad * wn[e];
    }
    #pragma unroll
    for (int e = 0; e < 4; ++e) {
      float v = out[e];
      out[e] = v > 0.0f ? v : (__expf(v) - 1.0f);
    }
    *(float4*)(Hout + ((size_t)b * NT + n0 + r) * DD + e0) =
        make_float4(out[0], out[1], out[2], out[3]);
  }
}

extern "C" void kernel_launch(void* const* d_in, const int* in_sizes, int n_in,
                              void* d_out, int out_size) {
  (void)in_sizes; (void)n_in; (void)out_size;
  const float* X  = (const float*)d_in[0];
  const float* Ws = (const float*)d_in[1];   // [2,32,32]
  const float* Wn = (const float*)d_in[2];   // [2,32,32]
  const float* bb = (const float*)d_in[3];   // [2,32]
  float* out = (float*)d_out;

  cudaFuncSetAttribute(gnn_main,
                       cudaFuncAttributeMaxDynamicSharedMemorySize, SMEM_TOTAL);

  dim3 pgrid(NT / 64, NB), pblk(256);
  dim3 grid(NT / BN, NB), blk(NTHREADS);

  prep_kernel<<<pgrid, pblk>>>(X, 1);                 // g_x*, g_hthi (H = X)
  gnn_main<<<grid, blk, SMEM_TOTAL>>>(X, Ws, Wn, bb, nullptr);          // -> g_h1
  prep_kernel<<<pgrid, pblk>>>(nullptr, 0);           // g_hthi from g_h1
  gnn_main<<<grid, blk, SMEM_TOTAL>>>(nullptr, Ws + 1024, Wn + 1024, bb + 32, out);
}

// round 7
// speedup vs baseline: 6.5350x; 1.2742x over previous
#include <cuda_runtime.h>
#include <cuda_fp16.h>
#include <cstdint>

#define NT 2560
#define DD 32
#define NB 4
#define BN 32
#define BM 128
#define NITER (NT / BM)   // 20
#define NTHREADS 256

// ---- smem byte offsets (main kernel) ----
#define SM_XNH 0
#define SM_BUF 2560
#define OFF_XMH 0
#define OFF_HTH 10240
#define BUFSZ   18944                 // per pipeline stage (XM hi + HT hi)
#define SM_W    (SM_BUF + 2 * BUFSZ)  // 40448
#define SM_AGG  SM_BUF                // agg reuses buf region after loop
#define SMEM_TOTAL (SM_W + 8320)      // 48768

// ---- device globals (allocation-free scratch) ----
__device__ float    g_h1 [NB * NT * DD];
__device__ uint32_t g_xhi[NB * NT * DD / 2];   // X fp16x2 [b][row][16]
__device__ uint32_t g_hthi[NB * DD * NT / 2];  // H^T fp16x2 [b][d][1280]

__device__ __forceinline__ uint32_t smem_u32(const void* p) {
  uint32_t a;
  asm("{ .reg .u64 t; cvta.to.shared.u64 t, %1; cvt.u32.u64 %0, t; }" : "=r"(a) : "l"(p));
  return a;
}
__device__ __forceinline__ void mma16816(float c[4], const uint32_t a[4],
                                         const uint32_t b[2]) {
  asm volatile(
      "mma.sync.aligned.m16n8k16.row.col.f32.f16.f16.f32 "
      "{%0,%1,%2,%3}, {%4,%5,%6,%7}, {%8,%9}, {%0,%1,%2,%3};"
      : "+f"(c[0]), "+f"(c[1]), "+f"(c[2]), "+f"(c[3])
      : "r"(a[0]), "r"(a[1]), "r"(a[2]), "r"(a[3]), "r"(b[0]), "r"(b[1]));
}
__device__ __forceinline__ void ldsm4(uint32_t r[4], uint32_t addr) {
  asm volatile("ldmatrix.sync.aligned.m8n8.x4.shared.b16 {%0,%1,%2,%3}, [%4];"
               : "=r"(r[0]), "=r"(r[1]), "=r"(r[2]), "=r"(r[3]) : "r"(addr));
}
__device__ __forceinline__ void cp16(uint32_t dst, const void* src) {
  asm volatile("cp.async.cg.shared.global [%0], [%1], 16;" :: "r"(dst), "l"(src));
}
#define CP_COMMIT() asm volatile("cp.async.commit_group;")
template <int N> __device__ __forceinline__ void cp_wait() {
  asm volatile("cp.async.wait_group %0;" :: "n"(N));
}
__device__ __forceinline__ float tanh_relu(float s) {
  float r = fmaxf(s, 0.0f), v;
  asm("tanh.approx.f32 %0, %1;" : "=f"(v) : "f"(r));
  return v;
}
__device__ __forceinline__ uint32_t pack_h2(float x, float y) {
  __half2 h = __floats2half2_rn(x, y);
  return *reinterpret_cast<uint32_t*>(&h);
}

// ---- prep: fp16-convert rows (optional write) + write transposed fp16 ----
__global__ void prep_kernel(const float* __restrict__ src_p, int write_x) {
  __shared__ uint32_t sxh[64][20];
  const float* src = src_p ? src_p : (const float*)g_h1;
  const int t = threadIdx.x, b = blockIdx.y, r0 = blockIdx.x * 64;
  {
    const int row = t >> 2, q = t & 3;
    const float4* p = (const float4*)(src + ((size_t)b * NT + r0 + row) * DD + q * 8);
    float4 v0 = p[0], v1 = p[1];
    uint4 hv = make_uint4(pack_h2(v0.x, v0.y), pack_h2(v0.z, v0.w),
                          pack_h2(v1.x, v1.y), pack_h2(v1.z, v1.w));
    *(uint4*)&sxh[row][q * 4] = hv;
    if (write_x) {
      size_t xi = ((size_t)b * NT + r0 + row) * 16 + q * 4;
      *(uint4*)&g_xhi[xi] = hv;
    }
  }
  __syncthreads();
  {
    const int d = t >> 3;
    const uint32_t sh = (d & 1) * 16;
    const size_t obase = ((size_t)b * DD + d) * (NT / 2) + (r0 >> 1);
    #pragma unroll
    for (int j = 0; j < 4; ++j) {
      const int p = (t & 7) * 4 + j;
      uint32_t h0 = (sxh[2 * p][d >> 1] >> sh) & 0xffffu;
      uint32_t h1 = (sxh[2 * p + 1][d >> 1] >> sh) & 0xffffu;
      g_hthi[obase + p] = h0 | (h1 << 16);
    }
  }
}

// ---- main fused layer ----
__global__ __launch_bounds__(NTHREADS, 3)
void gnn_main(const float* __restrict__ hin_p,
              const float* __restrict__ Ws, const float* __restrict__ Wn,
              const float* __restrict__ bias, float* __restrict__ hout_p)
{
  extern __shared__ char sm[];
  const uint32_t sb = smem_u32(sm);
  const int t = threadIdx.x, lane = t & 31, wid = t >> 5;
  const int wr = wid >> 2, wc = wid & 3, g = lane >> 2, tig = lane & 3;
  const int bx = blockIdx.x, b = blockIdx.y;
  const int n0 = bx * BN;
  const int mtdiag = bx >> 2, doff = (bx & 3) * 32;

  const float* Hin  = hin_p  ? hin_p  : (const float*)g_h1;
  float*       Hout = hout_p ? hout_p : g_h1;

  // weights -> smem
  float* sW = (float*)(sm + SM_W);
  for (int i = t; i < 2 * DD * DD + DD; i += NTHREADS) {
    float v;
    if (i < 1024)      v = Ws[i];
    else if (i < 2048) v = Wn[i - 1024];
    else               v = bias[i - 2048];
    sW[i] = v;
  }
  // Xn tile (persistent): 32 rows x 64B
  {
    const int row = t >> 3, q = t & 7;
    const size_t xi = ((size_t)b * NT + n0 + row) * 16 + q * 2;
    *(uint2*)(sm + SM_XNH + row * 80 + q * 8) = *(const uint2*)(g_xhi + xi);
  }

  // tile-issue via cp.async (4x16B per thread)
  auto issue = [&](int mt) {
    const int m0 = mt * BM;
    const uint32_t base = sb + SM_BUF + (uint32_t)(mt & 1) * BUFSZ;
    const size_t xbase = ((size_t)b * NT + m0) * 16;
    const size_t hbase = (size_t)b * DD * (NT / 2) + (m0 >> 1);
    #pragma unroll
    for (int i = 0; i < 2; ++i) {
      const int c = t + i * 256;
      const int row = c >> 2, q = c & 3;
      cp16(base + OFF_XMH + row * 80 + q * 16, g_xhi + xbase + row * 16 + q * 4);
      const int d = c >> 4, q2 = c & 15;
      cp16(base + OFF_HTH + d * 272 + q2 * 16, g_hthi + hbase + (size_t)d * (NT / 2) + q2 * 4);
    }
    CP_COMMIT();
  };

  // ---- ldmatrix lane addresses ----
  const uint32_t a_addr = sb + SM_XNH +
      (uint32_t)(16 * wr + 8 * ((lane >> 3) & 1) + (lane & 7)) * 80u +
      (uint32_t)(lane >> 4) * 16u;
  const uint32_t b1_addr = OFF_XMH +
      (uint32_t)(32 * wc + 8 * (lane >> 4) + (lane & 7)) * 80u +
      (uint32_t)((lane >> 3) & 1) * 16u;
  const uint32_t b2_addr = OFF_HTH +
      (uint32_t)(8 * (lane >> 4) + (lane & 7)) * 272u +
      (uint32_t)(64 * wc) + (uint32_t)((lane >> 3) & 1) * 16u;

  float acc2[4][4];
  #pragma unroll
  for (int nc = 0; nc < 4; ++nc)
    #pragma unroll
    for (int e = 0; e < 4; ++e) acc2[nc][e] = 0.0f;

  issue(0);
  __syncthreads();                       // Xn tile + weights visible

  // ---- hoisted loop-invariant A fragments (Xn) ----
  uint32_t AH[2][4];
  ldsm4(AH[0], a_addr);
  ldsm4(AH[1], a_addr + 32);

  for (int mt = 0; mt < NITER; ++mt) {
    if (mt + 1 < NITER) { issue(mt + 1); cp_wait<1>(); }
    else                { cp_wait<0>(); }
    __syncthreads();

    const uint32_t buf = sb + SM_BUF + (uint32_t)(mt & 1) * BUFSZ;
    const bool diag = (mt == mtdiag);

    // ---- load all B fragments up front (max MLP) ----
    uint32_t BH[2][2][4];    // [kt][pair]
    uint32_t BH2[2][2][4];   // [kt][pair]
    #pragma unroll
    for (int kt = 0; kt < 2; ++kt)
      #pragma unroll
      for (int p = 0; p < 2; ++p) {
        ldsm4(BH[kt][p],  buf + b1_addr + p * 1280u + kt * 32u);
        ldsm4(BH2[kt][p], buf + b2_addr + p * 4352u + kt * 32u);
      }

    // ---- phase 1: S[32x128] chunk per warp (fp16) ----
    float acc[4][4];
    #pragma unroll
    for (int mc = 0; mc < 4; ++mc)
      #pragma unroll
      for (int e = 0; e < 4; ++e) acc[mc][e] = 0.0f;

    #pragma unroll
    for (int kt = 0; kt < 2; ++kt)
      #pragma unroll
      for (int mc = 0; mc < 4; ++mc)
        mma16816(acc[mc], AH[kt], &BH[kt][mc >> 1][(mc & 1) * 2]);

    // ---- nonlinearity + self-loop; C -> phase-2 A frags ----
    uint32_t sA2[8];
    #pragma unroll
    for (int mc = 0; mc < 4; ++mc) {
      float v0 = tanh_relu(acc[mc][0]);
      float v1 = tanh_relu(acc[mc][1]);
      float v2 = tanh_relu(acc[mc][2]);
      float v3 = tanh_relu(acc[mc][3]);
      if (diag) {
        const int nl = 16 * wr + g;
        const int ml = 32 * wc + 8 * mc + 2 * tig;
        if (ml     == nl + doff)     v0 += 0.5f;
        if (ml + 1 == nl + doff)     v1 += 0.5f;
        if (ml     == nl + 8 + doff) v2 += 0.5f;
        if (ml + 1 == nl + 8 + doff) v3 += 0.5f;
      }
      sA2[2 * mc]     = pack_h2(v0, v1);
      sA2[2 * mc + 1] = pack_h2(v2, v3);
    }

    // ---- phase 2: agg += S x H ----
    #pragma unroll
    for (int kt = 0; kt < 2; ++kt)
      #pragma unroll
      for (int nc = 0; nc < 4; ++nc)
        mma16816(acc2[nc], &sA2[4 * kt], &BH2[kt][nc >> 1][(nc & 1) * 2]);

    __syncthreads();
  }

  // ---- cross-warp reduction of agg (4 m-slices) ----
  float* aggbuf = (float*)(sm + SM_AGG);
  {
    float* p = aggbuf + wc * 1024;
    const int nl = 16 * wr + g;
    #pragma unroll
    for (int nc = 0; nc < 4; ++nc) {
      const int d0 = 8 * nc + 2 * tig;
      p[nl * 32 + d0]           = acc2[nc][0];
      p[nl * 32 + d0 + 1]       = acc2[nc][1];
      p[(nl + 8) * 32 + d0]     = acc2[nc][2];
      p[(nl + 8) * 32 + d0 + 1] = acc2[nc][3];
    }
  }
  __syncthreads();
  {
    float4* a4 = (float4*)aggbuf;
    float4 s = a4[t], s1 = a4[t + 256], s2 = a4[t + 512], s3 = a4[t + 768];
    a4[t] = make_float4(s.x + s1.x + s2.x + s3.x, s.y + s1.y + s2.y + s3.y,
                        s.z + s1.z + s2.z + s3.z, s.w + s1.w + s2.w + s3.w);
  }
  __syncthreads();

  // ---- epilogue: out = elu(h*Ws + agg*Wn + b) ----
  {
    const int r = t >> 3, e0 = (t & 7) * 4;
    float h[DD];
    const float4* hr = (const float4*)(Hin + ((size_t)b * NT + n0 + r) * DD);
    #pragma unroll
    for (int q = 0; q < 8; ++q) {
      float4 v = hr[q];
      h[4 * q] = v.x; h[4 * q + 1] = v.y; h[4 * q + 2] = v.z; h[4 * q + 3] = v.w;
    }
    float out[4];
    #pragma unroll
    for (int e = 0; e < 4; ++e) out[e] = sW[2048 + e0 + e];
    const float* ag = aggbuf + r * DD;
    #pragma unroll
    for (int d = 0; d < DD; ++d) {
      const float hd = h[d];
      const float ad = ag[d];
      const float* ws = sW + d * DD + e0;
      const float* wn = sW + 1024 + d * DD + e0;
      #pragma unroll
      for (int e = 0; e < 4; ++e) out[e] += hd * ws[e] + ad * wn[e];
    }
    #pragma unroll
    for (int e = 0; e < 4; ++e) {
      float v = out[e];
      out[e] = v > 0.0f ? v : (__expf(v) - 1.0f);
    }
    *(float4*)(Hout + ((size_t)b * NT + n0 + r) * DD + e0) =
        make_float4(out[0], out[1], out[2], out[3]);
  }
}

extern "C" void kernel_launch(void* const* d_in, const int* in_sizes, int n_in,
                              void* d_out, int out_size) {
  (void)in_sizes; (void)n_in; (void)out_size;
  const float* X  = (const float*)d_in[0];
  const float* Ws = (const float*)d_in[1];   // [2,32,32]
  const float* Wn = (const float*)d_in[2];   // [2,32,32]
  const float* bb = (const float*)d_in[3];   // [2,32]
  float* out = (float*)d_out;

  cudaFuncSetAttribute(gnn_main,
                       cudaFuncAttributeMaxDynamicSharedMemorySize, SMEM_TOTAL);

  dim3 pgrid(NT / 64, NB), pblk(256);
  dim3 grid(NT / BN, NB), blk(NTHREADS);

  prep_kernel<<<pgrid, pblk>>>(X, 1);                 // g_xhi, g_hthi (H = X)
  gnn_main<<<grid, blk, SMEM_TOTAL>>>(X, Ws, Wn, bb, nullptr);          // -> g_h1
  prep_kernel<<<pgrid, pblk>>>(nullptr, 0);           // g_hthi from g_h1
  gnn_main<<<grid, blk, SMEM_TOTAL>>>(nullptr, Ws + 1024, Wn + 1024, bb + 32, out);
}